// round 13
// baseline (speedup 1.0000x reference)
#include <cuda_runtime.h>
#include <cuda_bf16.h>
#include <cstdint>

// Problem constants
#define B_SZ   16
#define CIN    128
#define COUT   128
#define HD     512
#define HW     128      // input H = W
#define OHW    126      // output H = W (VALID conv, K=3)
#define REM    1152     // CIN * 9
#define WSIZE  147456   // COUT * REM

// Single dynamic-smem symbol for the whole TU
extern __shared__ __align__(16) char dsm[];

// ---------------------------------------------------------------------------
// Device-global scratch (no allocation allowed anywhere)
// ---------------------------------------------------------------------------
// conv weights bf16 hi/lo, layout [b][co][k], k = tap*128 + ci (tap-major)
__device__ __align__(16) __nv_bfloat16 g_wh[B_SZ * WSIZE];
__device__ __align__(16) __nv_bfloat16 g_wl[B_SZ * WSIZE];
// x transposed to [b][ih][iw][ci] bf16 hi/lo (+pad: conv may read past end)
__device__ __align__(16) __nv_bfloat16 g_xh[B_SZ * HW * HW * CIN + 1024];
__device__ __align__(16) __nv_bfloat16 g_xl[B_SZ * HW * HW * CIN + 1024];
__device__ float g_bias[B_SZ * COUT];

// ---------------------------------------------------------------------------
// helpers
// ---------------------------------------------------------------------------
__device__ __forceinline__ uint32_t smem_to_u32(const void* p) {
    uint32_t a;
    asm("{ .reg .u64 t; cvta.to.shared.u64 t, %1; cvt.u32.u64 %0, t; }"
        : "=r"(a) : "l"(p));
    return a;
}
__device__ __forceinline__ void cp16(void* dst, const void* src) {
    uint32_t d = smem_to_u32(dst);
    asm volatile("cp.async.cg.shared.global [%0], [%1], 16;"
                 :: "r"(d), "l"(src) : "memory");
}
#define CP_COMMIT()  asm volatile("cp.async.commit_group;" ::: "memory")
#define CP_WAIT(n)   asm volatile("cp.async.wait_group %0;" :: "n"(n) : "memory")

// mma.sync m16n8k16 row.col bf16 -> f32 accumulate (plain sm_80+ HMMA path)
__device__ __forceinline__ void mma16816(float* c, const uint32_t* a,
                                         const uint32_t* b) {
    asm volatile(
        "mma.sync.aligned.m16n8k16.row.col.f32.bf16.bf16.f32 "
        "{%0,%1,%2,%3}, {%4,%5,%6,%7}, {%8,%9}, {%0,%1,%2,%3};"
        : "+f"(c[0]), "+f"(c[1]), "+f"(c[2]), "+f"(c[3])
        : "r"(a[0]), "r"(a[1]), "r"(a[2]), "r"(a[3]), "r"(b[0]), "r"(b[1]));
}

// f32x2 helpers (hyper GEMM keeps the proven FFMA2 path)
__device__ __forceinline__ void fma2(unsigned long long& d,
                                     unsigned long long a, unsigned long long b) {
    asm("fma.rn.f32x2 %0, %1, %2, %0;" : "+l"(d) : "l"(a), "l"(b));
}
__device__ __forceinline__ unsigned long long dup2(float v) {
    unsigned long long r; unsigned u = __float_as_uint(v);
    asm("mov.b64 %0, {%1, %1};" : "=l"(r) : "r"(u));
    return r;
}
__device__ __forceinline__ void unpack2(unsigned long long v, float& lo, float& hi) {
    asm("mov.b64 {%0, %1}, %2;" : "=f"(lo), "=f"(hi) : "l"(v));
}

// ---------------------------------------------------------------------------
// Kernel 1: hyper GEMM.  w[b,n] = h[b]·Wh[n] + bh[n]  (proven, 106us)
// Epilogue writes bf16 hi/lo into g_wh/g_wl at [b][co][k], k = tap*128 + ci.
// ---------------------------------------------------------------------------
__global__ __launch_bounds__(256, 1)
void hyper_gemm_kernel(const float* __restrict__ Wh,
                       const float* __restrict__ h,
                       const float* __restrict__ bh) {
    float* sw = reinterpret_cast<float*>(dsm);               // [1024][33]
    float* hs = reinterpret_cast<float*>(dsm) + 1024 * 33;   // [32][16]

    const int t  = threadIdx.x;
    const int n0 = blockIdx.x * 1024;

    unsigned long long acc[32];
#pragma unroll
    for (int i = 0; i < 32; i++) acc[i] = 0ULL;

    for (int k0 = 0; k0 < HD; k0 += 32) {
        __syncthreads();
#pragma unroll
        for (int q = 0; q < 2; q++) {
            int idx = t + q * 256;
            hs[idx] = h[(idx & 15) * HD + k0 + (idx >> 4)];
        }
#pragma unroll
        for (int r = 0; r < 32; r++) {
            int linear = r * 256 + t;
            int n = linear >> 3, c = linear & 7;
            float4 v = reinterpret_cast<const float4*>(Wh)
                           [(size_t)(n0 + n) * (HD / 4) + (k0 >> 2) + c];
            float* dst = sw + n * 33 + c * 4;
            dst[0] = v.x; dst[1] = v.y; dst[2] = v.z; dst[3] = v.w;
        }
        __syncthreads();

#pragma unroll
        for (int kk = 0; kk < 32; kk++) {
            unsigned long long hv[8];
            const unsigned long long* hp =
                reinterpret_cast<const unsigned long long*>(hs + kk * 16);
#pragma unroll
            for (int bb = 0; bb < 8; bb++) hv[bb] = hp[bb];
            unsigned long long wv[4];
#pragma unroll
            for (int j = 0; j < 4; j++)
                wv[j] = dup2(sw[(t + 256 * j) * 33 + kk]);
#pragma unroll
            for (int bb = 0; bb < 8; bb++)
#pragma unroll
                for (int j = 0; j < 4; j++)
                    fma2(acc[bb * 4 + j], hv[bb], wv[j]);
        }
    }

#pragma unroll
    for (int j = 0; j < 4; j++) {
        int n   = n0 + t + 256 * j;
        float bv = bh[n];
        int co  = n / REM;
        int rem = n - co * REM;
        int ci  = rem / 9;
        int tap = rem - ci * 9;
        int k   = tap * 128 + ci;
#pragma unroll
        for (int bb = 0; bb < 8; bb++) {
            float lo, hi;
            unpack2(acc[bb * 4 + j], lo, hi);
            float w0 = lo + bv, w1 = hi + bv;
            size_t i0 = ((size_t)((2 * bb) * COUT + co)) * REM + k;
            size_t i1 = ((size_t)((2 * bb + 1) * COUT + co)) * REM + k;
            __nv_bfloat16 h0 = __float2bfloat16(w0);
            __nv_bfloat16 h1 = __float2bfloat16(w1);
            g_wh[i0] = h0;
            g_wl[i0] = __float2bfloat16(w0 - __bfloat162float(h0));
            g_wh[i1] = h1;
            g_wl[i1] = __float2bfloat16(w1 - __bfloat162float(h1));
        }
    }
}

// ---------------------------------------------------------------------------
// Kernel 2: x transpose NCHW -> [b][ih][iw][ci], bf16 hi/lo split
// ---------------------------------------------------------------------------
__global__ __launch_bounds__(256)
void xpose_kernel(const float* __restrict__ x) {
    __shared__ float ts[32][33];
    const int ih = blockIdx.x, b = blockIdx.y;
    const int t = threadIdx.x, j = t & 31, g = t >> 5;

    for (int cit = 0; cit < 4; cit++)
        for (int iwt = 0; iwt < 4; iwt++) {
            __syncthreads();
#pragma unroll
            for (int ii = 0; ii < 4; ii++) {
                int ci = cit * 32 + g + ii * 8;
                ts[g + ii * 8][j] =
                    x[(((size_t)b * CIN + ci) * HW + ih) * HW + iwt * 32 + j];
            }
            __syncthreads();
#pragma unroll
            for (int ii = 0; ii < 4; ii++) {
                int iwl = g + ii * 8;
                float v = ts[j][iwl];
                __nv_bfloat16 hi = __float2bfloat16(v);
                __nv_bfloat16 lo = __float2bfloat16(v - __bfloat162float(hi));
                size_t dst = (((size_t)b * HW + ih) * HW + iwt * 32 + iwl) * CIN
                             + cit * 32 + j;
                g_xh[dst] = hi;
                g_xl[dst] = lo;
            }
        }
}

// ---------------------------------------------------------------------------
// Kernel 3: per-sample bias (unchanged)
// ---------------------------------------------------------------------------
__global__ void hyper_bias_kernel(const float* __restrict__ h,
                                  const float* __restrict__ Wb,
                                  const float* __restrict__ bb) {
    int out  = blockIdx.x * 8 + (threadIdx.x >> 5);
    int lane = threadIdx.x & 31;
    int b  = out >> 7;
    int co = out & 127;
    float s = 0.f;
    for (int k = lane; k < HD; k += 32)
        s += h[b * HD + k] * Wb[co * HD + k];
#pragma unroll
    for (int o = 16; o > 0; o >>= 1) s += __shfl_xor_sync(0xffffffffu, s, o);
    if (lane == 0) g_bias[out] = s + bb[co];
}

// ---------------------------------------------------------------------------
// Kernel 4: HMMA conv, now 512 threads / 16 warps (4x4 warp grid).
// CTA = (oh, b): M=128 co x N=128 ow, K=1152 tap-major; warp tile 32x32.
// 18 chunks of KC=64, cp.async double buffer, 3 bf16-split passes.
// Doubling warps/SMSP (2 -> 4) hides the HMMA dependency latency that held
// tensor at 55% in R12.
// ---------------------------------------------------------------------------
#define NCH   18
#define AROW  72                 // bf16 elems per smem row (64 data + 8 pad)
#define MATE  (128 * AROW)       // elems per matrix  (9216)
#define STGE  (4 * MATE)         // elems per stage   (Ah|Al|Bh|Bl)
#define CONV_SMEM (2 * STGE * 2) // bytes = 147456

__global__ __launch_bounds__(512, 1)
void conv_mma_kernel(float* __restrict__ y) {
    __nv_bfloat16* sm = reinterpret_cast<__nv_bfloat16*>(dsm);
    const int t    = threadIdx.x;
    const int lane = t & 31, wid = t >> 5;
    const int g    = lane >> 2, tq = lane & 3;
    const int wrow = wid >> 2, wcol = wid & 3;   // 4x4 warp grid
    const int oh   = blockIdx.x;        // 0..125
    const int b    = blockIdx.y;        // 0..15

    const __nv_bfloat16* whp = g_wh + (size_t)b * WSIZE;
    const __nv_bfloat16* wlp = g_wl + (size_t)b * WSIZE;

    float acc[2][4][4];
#pragma unroll
    for (int mi = 0; mi < 2; mi++)
#pragma unroll
        for (int ni = 0; ni < 4; ni++)
#pragma unroll
            for (int q = 0; q < 4; q++) acc[mi][ni][q] = 0.f;

    auto load_stage = [&](int s, int kc) {
        const int tap = kc >> 1, ci0 = (kc & 1) * 64;
        const int kh = tap / 3, kw = tap - 3 * kh;
        __nv_bfloat16* st = sm + s * STGE;
        const size_t xoff = (((size_t)(b * HW) + oh + kh) * HW + kw) * CIN + ci0;
        const __nv_bfloat16* xh = g_xh + xoff;
        const __nv_bfloat16* xl = g_xl + xoff;
#pragma unroll
        for (int i = 0; i < 2; i++) {
            int idx = t + i * 512;
            int row = idx >> 3, c = idx & 7;    // row: co or px; c: 16B column
            int so = row * AROW + c * 8;
            int wo = row * REM + kc * 64 + c * 8;
            cp16(st + so,            whp + wo);
            cp16(st + MATE + so,     wlp + wo);
            size_t xo = (size_t)row * CIN + c * 8;   // row = px = ow
            cp16(st + 2 * MATE + so, xh + xo);
            cp16(st + 3 * MATE + so, xl + xo);
        }
        CP_COMMIT();
    };

    load_stage(0, 0);

    for (int kc = 0; kc < NCH; kc++) {
        if (kc + 1 < NCH) { load_stage((kc + 1) & 1, kc + 1); CP_WAIT(1); }
        else              { CP_WAIT(0); }
        __syncthreads();

        const __nv_bfloat16* st = sm + (kc & 1) * STGE;
        const __nv_bfloat16* Ah = st;
        const __nv_bfloat16* Al = st + MATE;
        const __nv_bfloat16* Bh = st + 2 * MATE;
        const __nv_bfloat16* Bl = st + 3 * MATE;

#pragma unroll
        for (int ks = 0; ks < 4; ks++) {
            const int kw0 = ks * 16 + 2 * tq;
            uint32_t ahf[2][4], alf[2][4], bhf[4][2], blf[4][2];
#pragma unroll
            for (int mi = 0; mi < 2; mi++) {
                int r0 = wrow * 32 + mi * 16 + g;
                const __nv_bfloat16* p0 = Ah + r0 * AROW + kw0;
                ahf[mi][0] = *(const uint32_t*)p0;
                ahf[mi][1] = *(const uint32_t*)(p0 + 8 * AROW);
                ahf[mi][2] = *(const uint32_t*)(p0 + 8);
                ahf[mi][3] = *(const uint32_t*)(p0 + 8 * AROW + 8);
                const __nv_bfloat16* p1 = Al + r0 * AROW + kw0;
                alf[mi][0] = *(const uint32_t*)p1;
                alf[mi][1] = *(const uint32_t*)(p1 + 8 * AROW);
                alf[mi][2] = *(const uint32_t*)(p1 + 8);
                alf[mi][3] = *(const uint32_t*)(p1 + 8 * AROW + 8);
            }
#pragma unroll
            for (int ni = 0; ni < 4; ni++) {
                int n0 = wcol * 32 + ni * 8 + g;
                const __nv_bfloat16* p0 = Bh + n0 * AROW + kw0;
                bhf[ni][0] = *(const uint32_t*)p0;
                bhf[ni][1] = *(const uint32_t*)(p0 + 8);
                const __nv_bfloat16* p1 = Bl + n0 * AROW + kw0;
                blf[ni][0] = *(const uint32_t*)p1;
                blf[ni][1] = *(const uint32_t*)(p1 + 8);
            }
#pragma unroll
            for (int mi = 0; mi < 2; mi++)
#pragma unroll
                for (int ni = 0; ni < 4; ni++) {
                    mma16816(acc[mi][ni], ahf[mi], bhf[ni]);  // wh*xh
                    mma16816(acc[mi][ni], ahf[mi], blf[ni]);  // wh*xl
                    mma16816(acc[mi][ni], alf[mi], bhf[ni]);  // wl*xh
                }
        }
        __syncthreads();
    }

    // Epilogue: + per-sample bias, guarded stores (ow < 126)
    const float* bp = g_bias + b * COUT;
#pragma unroll
    for (int mi = 0; mi < 2; mi++) {
        int co0 = wrow * 32 + mi * 16 + g;       // c0/c1 rows; c2/c3 at co0+8
        float bias0 = bp[co0], bias1 = bp[co0 + 8];
        float* y0 = y + (((size_t)(b * COUT) + co0) * OHW + oh) * OHW;
        float* y1 = y0 + (size_t)8 * OHW * OHW;
#pragma unroll
        for (int ni = 0; ni < 4; ni++) {
            int ow = wcol * 32 + ni * 8 + 2 * tq;
            if (ow < OHW) {
                y0[ow] = acc[mi][ni][0] + bias0;
                y1[ow] = acc[mi][ni][2] + bias1;
            }
            if (ow + 1 < OHW) {
                y0[ow + 1] = acc[mi][ni][1] + bias0;
                y1[ow + 1] = acc[mi][ni][3] + bias1;
            }
        }
    }
}

// ---------------------------------------------------------------------------
// Launch. Inputs: x, h, Wh, bh, Wb, bb. Output float32.
// ---------------------------------------------------------------------------
extern "C" void kernel_launch(void* const* d_in, const int* in_sizes, int n_in,
                              void* d_out, int out_size) {
    const float* x  = (const float*)d_in[0];
    const float* h  = (const float*)d_in[1];
    const float* Wh = (const float*)d_in[2];
    const float* bh = (const float*)d_in[3];
    const float* Wb = (const float*)d_in[4];
    const float* bb = (const float*)d_in[5];
    float* y = (float*)d_out;

    const int gemm_smem = (1024 * 33 + 32 * 16) * (int)sizeof(float);  // 137216
    cudaFuncSetAttribute(hyper_gemm_kernel,
                         cudaFuncAttributeMaxDynamicSharedMemorySize, gemm_smem);
    cudaFuncSetAttribute(conv_mma_kernel,
                         cudaFuncAttributeMaxDynamicSharedMemorySize, CONV_SMEM);

    hyper_gemm_kernel<<<WSIZE / 1024, 256, gemm_smem>>>(Wh, h, bh);
    xpose_kernel<<<dim3(HW, B_SZ), 256>>>(x);
    hyper_bias_kernel<<<(B_SZ * COUT) / 8, 256>>>(h, Wb, bb);
    conv_mma_kernel<<<dim3(OHW, B_SZ), 512, CONV_SMEM>>>(y);
}

// round 14
// speedup vs baseline: 1.3344x; 1.3344x over previous
#include <cuda_runtime.h>
#include <cuda_bf16.h>
#include <cuda_fp16.h>
#include <cstdint>

// Problem constants
#define B_SZ   16
#define CIN    128
#define COUT   128
#define HD     512
#define HW     128      // input H = W
#define OHW    126      // output H = W (VALID conv, K=3)
#define REM    1152     // CIN * 9
#define WSIZE  147456   // COUT * REM

// Single dynamic-smem symbol for the whole TU
extern __shared__ __align__(16) char dsm[];

// ---------------------------------------------------------------------------
// Device-global scratch (no allocation allowed anywhere)
// ---------------------------------------------------------------------------
// conv weights fp16 hi/lo, layout [b][co][k], k = tap*128 + ci (tap-major)
__device__ __align__(16) __half g_wh[B_SZ * WSIZE];
__device__ __align__(16) __half g_wl[B_SZ * WSIZE];
// x transposed to [b][ih][iw][ci] fp16 (+pad: conv may read past end)
__device__ __align__(16) __half g_xh[B_SZ * HW * HW * CIN + 1024];
__device__ float g_bias[B_SZ * COUT];

// ---------------------------------------------------------------------------
// helpers
// ---------------------------------------------------------------------------
__device__ __forceinline__ uint32_t smem_to_u32(const void* p) {
    uint32_t a;
    asm("{ .reg .u64 t; cvta.to.shared.u64 t, %1; cvt.u32.u64 %0, t; }"
        : "=r"(a) : "l"(p));
    return a;
}
__device__ __forceinline__ void cp16(void* dst, const void* src) {
    uint32_t d = smem_to_u32(dst);
    asm volatile("cp.async.cg.shared.global [%0], [%1], 16;"
                 :: "r"(d), "l"(src) : "memory");
}
#define CP_COMMIT()  asm volatile("cp.async.commit_group;" ::: "memory")
#define CP_WAIT(n)   asm volatile("cp.async.wait_group %0;" :: "n"(n) : "memory")

// mma.sync m16n8k16 row.col fp16 -> f32 accumulate
__device__ __forceinline__ void mma16816(float* c, const uint32_t* a,
                                         const uint32_t* b) {
    asm volatile(
        "mma.sync.aligned.m16n8k16.row.col.f32.f16.f16.f32 "
        "{%0,%1,%2,%3}, {%4,%5,%6,%7}, {%8,%9}, {%0,%1,%2,%3};"
        : "+f"(c[0]), "+f"(c[1]), "+f"(c[2]), "+f"(c[3])
        : "r"(a[0]), "r"(a[1]), "r"(a[2]), "r"(a[3]), "r"(b[0]), "r"(b[1]));
}

// f32x2 helpers (hyper GEMM keeps the proven FFMA2 path)
__device__ __forceinline__ void fma2(unsigned long long& d,
                                     unsigned long long a, unsigned long long b) {
    asm("fma.rn.f32x2 %0, %1, %2, %0;" : "+l"(d) : "l"(a), "l"(b));
}
__device__ __forceinline__ unsigned long long dup2(float v) {
    unsigned long long r; unsigned u = __float_as_uint(v);
    asm("mov.b64 %0, {%1, %1};" : "=l"(r) : "r"(u));
    return r;
}
__device__ __forceinline__ void unpack2(unsigned long long v, float& lo, float& hi) {
    asm("mov.b64 {%0, %1}, %2;" : "=f"(lo), "=f"(hi) : "l"(v));
}

// ---------------------------------------------------------------------------
// Kernel 1: hyper GEMM.  w[b,n] = h[b]·Wh[n] + bh[n]  (proven, 106us)
// Epilogue writes fp16 hi/lo into g_wh/g_wl at [b][co][k], k = tap*128 + ci.
// ---------------------------------------------------------------------------
__global__ __launch_bounds__(256, 1)
void hyper_gemm_kernel(const float* __restrict__ Wh,
                       const float* __restrict__ h,
                       const float* __restrict__ bh) {
    float* sw = reinterpret_cast<float*>(dsm);               // [1024][33]
    float* hs = reinterpret_cast<float*>(dsm) + 1024 * 33;   // [32][16]

    const int t  = threadIdx.x;
    const int n0 = blockIdx.x * 1024;

    unsigned long long acc[32];
#pragma unroll
    for (int i = 0; i < 32; i++) acc[i] = 0ULL;

    for (int k0 = 0; k0 < HD; k0 += 32) {
        __syncthreads();
#pragma unroll
        for (int q = 0; q < 2; q++) {
            int idx = t + q * 256;
            hs[idx] = h[(idx & 15) * HD + k0 + (idx >> 4)];
        }
#pragma unroll
        for (int r = 0; r < 32; r++) {
            int linear = r * 256 + t;
            int n = linear >> 3, c = linear & 7;
            float4 v = reinterpret_cast<const float4*>(Wh)
                           [(size_t)(n0 + n) * (HD / 4) + (k0 >> 2) + c];
            float* dst = sw + n * 33 + c * 4;
            dst[0] = v.x; dst[1] = v.y; dst[2] = v.z; dst[3] = v.w;
        }
        __syncthreads();

#pragma unroll
        for (int kk = 0; kk < 32; kk++) {
            unsigned long long hv[8];
            const unsigned long long* hp =
                reinterpret_cast<const unsigned long long*>(hs + kk * 16);
#pragma unroll
            for (int bb = 0; bb < 8; bb++) hv[bb] = hp[bb];
            unsigned long long wv[4];
#pragma unroll
            for (int j = 0; j < 4; j++)
                wv[j] = dup2(sw[(t + 256 * j) * 33 + kk]);
#pragma unroll
            for (int bb = 0; bb < 8; bb++)
#pragma unroll
                for (int j = 0; j < 4; j++)
                    fma2(acc[bb * 4 + j], hv[bb], wv[j]);
        }
    }

#pragma unroll
    for (int j = 0; j < 4; j++) {
        int n   = n0 + t + 256 * j;
        float bv = bh[n];
        int co  = n / REM;
        int rem = n - co * REM;
        int ci  = rem / 9;
        int tap = rem - ci * 9;
        int k   = tap * 128 + ci;
#pragma unroll
        for (int bb = 0; bb < 8; bb++) {
            float lo, hi;
            unpack2(acc[bb * 4 + j], lo, hi);
            float w0 = lo + bv, w1 = hi + bv;
            size_t i0 = ((size_t)((2 * bb) * COUT + co)) * REM + k;
            size_t i1 = ((size_t)((2 * bb + 1) * COUT + co)) * REM + k;
            __half h0 = __float2half_rn(w0);
            __half h1 = __float2half_rn(w1);
            g_wh[i0] = h0;
            g_wl[i0] = __float2half_rn(w0 - __half2float(h0));
            g_wh[i1] = h1;
            g_wl[i1] = __float2half_rn(w1 - __half2float(h1));
        }
    }
}

// ---------------------------------------------------------------------------
// Kernel 2: x transpose NCHW -> [b][ih][iw][ci], fp16
// ---------------------------------------------------------------------------
__global__ __launch_bounds__(256)
void xpose_kernel(const float* __restrict__ x) {
    __shared__ float ts[32][33];
    const int ih = blockIdx.x, b = blockIdx.y;
    const int t = threadIdx.x, j = t & 31, g = t >> 5;

    for (int cit = 0; cit < 4; cit++)
        for (int iwt = 0; iwt < 4; iwt++) {
            __syncthreads();
#pragma unroll
            for (int ii = 0; ii < 4; ii++) {
                int ci = cit * 32 + g + ii * 8;
                ts[g + ii * 8][j] =
                    x[(((size_t)b * CIN + ci) * HW + ih) * HW + iwt * 32 + j];
            }
            __syncthreads();
#pragma unroll
            for (int ii = 0; ii < 4; ii++) {
                int iwl = g + ii * 8;
                size_t dst = (((size_t)b * HW + ih) * HW + iwt * 32 + iwl) * CIN
                             + cit * 32 + j;
                g_xh[dst] = __float2half_rn(ts[j][iwl]);
            }
        }
}

// ---------------------------------------------------------------------------
// Kernel 3: per-sample bias (unchanged)
// ---------------------------------------------------------------------------
__global__ void hyper_bias_kernel(const float* __restrict__ h,
                                  const float* __restrict__ Wb,
                                  const float* __restrict__ bb) {
    int out  = blockIdx.x * 8 + (threadIdx.x >> 5);
    int lane = threadIdx.x & 31;
    int b  = out >> 7;
    int co = out & 127;
    float s = 0.f;
    for (int k = lane; k < HD; k += 32)
        s += h[b * HD + k] * Wb[co * HD + k];
#pragma unroll
    for (int o = 16; o > 0; o >>= 1) s += __shfl_xor_sync(0xffffffffu, s, o);
    if (lane == 0) g_bias[out] = s + bb[co];
}

// ---------------------------------------------------------------------------
// Kernel 4: HMMA conv, fp16 2-pass split (wh*x + wl*x).
// CTA = (oh, b): M=128 co x N=128 ow, K=1152 tap-major. 256 thr, 8 warps,
// warp tile 64x32 (R12 shape — measured faster than 16-warp R13).
// 18 chunks of KC=64, cp.async double buffer; 2/3 the MMA count of R12/13.
// ---------------------------------------------------------------------------
#define NCH   18
#define AROW  72                 // fp16 elems per smem row (64 data + 8 pad)
#define MATE  (128 * AROW)       // elems per matrix  (9216)
#define STGE  (3 * MATE)         // elems per stage   (Ah|Al|B)
#define CONV_SMEM (2 * STGE * 2) // bytes = 110592

__global__ __launch_bounds__(256, 1)
void conv_mma_kernel(float* __restrict__ y) {
    __half* sm = reinterpret_cast<__half*>(dsm);
    const int t    = threadIdx.x;
    const int lane = t & 31, wid = t >> 5;
    const int g    = lane >> 2, tq = lane & 3;
    const int wrow = wid >> 2, wcol = wid & 3;   // 2x4 warp grid
    const int oh   = blockIdx.x;        // 0..125
    const int b    = blockIdx.y;        // 0..15

    const __half* whp = g_wh + (size_t)b * WSIZE;
    const __half* wlp = g_wl + (size_t)b * WSIZE;

    float acc[4][4][4];
#pragma unroll
    for (int mi = 0; mi < 4; mi++)
#pragma unroll
        for (int ni = 0; ni < 4; ni++)
#pragma unroll
            for (int q = 0; q < 4; q++) acc[mi][ni][q] = 0.f;

    auto load_stage = [&](int s, int kc) {
        const int tap = kc >> 1, ci0 = (kc & 1) * 64;
        const int kh = tap / 3, kw = tap - 3 * kh;
        __half* st = sm + s * STGE;
        const size_t xoff = (((size_t)(b * HW) + oh + kh) * HW + kw) * CIN + ci0;
        const __half* xh = g_xh + xoff;
#pragma unroll
        for (int i = 0; i < 4; i++) {
            int idx = t + i * 256;
            int row = idx >> 3, c = idx & 7;    // row: co or px; c: 16B column
            int so = row * AROW + c * 8;
            int wo = row * REM + kc * 64 + c * 8;
            cp16(st + so,            whp + wo);
            cp16(st + MATE + so,     wlp + wo);
            size_t xo = (size_t)row * CIN + c * 8;   // row = px = ow
            cp16(st + 2 * MATE + so, xh + xo);
        }
        CP_COMMIT();
    };

    load_stage(0, 0);

    for (int kc = 0; kc < NCH; kc++) {
        if (kc + 1 < NCH) { load_stage((kc + 1) & 1, kc + 1); CP_WAIT(1); }
        else              { CP_WAIT(0); }
        __syncthreads();

        const __half* st = sm + (kc & 1) * STGE;
        const __half* Ah = st;
        const __half* Al = st + MATE;
        const __half* Bx = st + 2 * MATE;

#pragma unroll
        for (int ks = 0; ks < 4; ks++) {
            const int kw0 = ks * 16 + 2 * tq;
            uint32_t ahf[4][4], alf[4][4], bf[4][2];
#pragma unroll
            for (int mi = 0; mi < 4; mi++) {
                int r0 = wrow * 64 + mi * 16 + g;
                const __half* p0 = Ah + r0 * AROW + kw0;
                ahf[mi][0] = *(const uint32_t*)p0;
                ahf[mi][1] = *(const uint32_t*)(p0 + 8 * AROW);
                ahf[mi][2] = *(const uint32_t*)(p0 + 8);
                ahf[mi][3] = *(const uint32_t*)(p0 + 8 * AROW + 8);
                const __half* p1 = Al + r0 * AROW + kw0;
                alf[mi][0] = *(const uint32_t*)p1;
                alf[mi][1] = *(const uint32_t*)(p1 + 8 * AROW);
                alf[mi][2] = *(const uint32_t*)(p1 + 8);
                alf[mi][3] = *(const uint32_t*)(p1 + 8 * AROW + 8);
            }
#pragma unroll
            for (int ni = 0; ni < 4; ni++) {
                int n0 = wcol * 32 + ni * 8 + g;
                const __half* p0 = Bx + n0 * AROW + kw0;
                bf[ni][0] = *(const uint32_t*)p0;
                bf[ni][1] = *(const uint32_t*)(p0 + 8);
            }
            // pass-major issue: each acc's 2 dependent HMMAs are 16 apart
#pragma unroll
            for (int mi = 0; mi < 4; mi++)
#pragma unroll
                for (int ni = 0; ni < 4; ni++)
                    mma16816(acc[mi][ni], ahf[mi], bf[ni]);  // wh*x
#pragma unroll
            for (int mi = 0; mi < 4; mi++)
#pragma unroll
                for (int ni = 0; ni < 4; ni++)
                    mma16816(acc[mi][ni], alf[mi], bf[ni]);  // wl*x
        }
        __syncthreads();
    }

    // Epilogue: + per-sample bias, guarded stores (ow < 126)
    const float* bp = g_bias + b * COUT;
#pragma unroll
    for (int mi = 0; mi < 4; mi++) {
        int co0 = wrow * 64 + mi * 16 + g;       // c0/c1 rows; c2/c3 at co0+8
        float bias0 = bp[co0], bias1 = bp[co0 + 8];
        float* y0 = y + (((size_t)(b * COUT) + co0) * OHW + oh) * OHW;
        float* y1 = y0 + (size_t)8 * OHW * OHW;
#pragma unroll
        for (int ni = 0; ni < 4; ni++) {
            int ow = wcol * 32 + ni * 8 + 2 * tq;
            if (ow < OHW) {
                y0[ow] = acc[mi][ni][0] + bias0;
                y1[ow] = acc[mi][ni][2] + bias1;
            }
            if (ow + 1 < OHW) {
                y0[ow + 1] = acc[mi][ni][1] + bias0;
                y1[ow + 1] = acc[mi][ni][3] + bias1;
            }
        }
    }
}

// ---------------------------------------------------------------------------
// Launch. Inputs: x, h, Wh, bh, Wb, bb. Output float32.
// ---------------------------------------------------------------------------
extern "C" void kernel_launch(void* const* d_in, const int* in_sizes, int n_in,
                              void* d_out, int out_size) {
    const float* x  = (const float*)d_in[0];
    const float* h  = (const float*)d_in[1];
    const float* Wh = (const float*)d_in[2];
    const float* bh = (const float*)d_in[3];
    const float* Wb = (const float*)d_in[4];
    const float* bb = (const float*)d_in[5];
    float* y = (float*)d_out;

    const int gemm_smem = (1024 * 33 + 32 * 16) * (int)sizeof(float);  // 137216
    cudaFuncSetAttribute(hyper_gemm_kernel,
                         cudaFuncAttributeMaxDynamicSharedMemorySize, gemm_smem);
    cudaFuncSetAttribute(conv_mma_kernel,
                         cudaFuncAttributeMaxDynamicSharedMemorySize, CONV_SMEM);

    hyper_gemm_kernel<<<WSIZE / 1024, 256, gemm_smem>>>(Wh, h, bh);
    xpose_kernel<<<dim3(HW, B_SZ), 256>>>(x);
    hyper_bias_kernel<<<(B_SZ * COUT) / 8, 256>>>(h, Wb, bb);
    conv_mma_kernel<<<dim3(OHW, B_SZ), 256, CONV_SMEM>>>(y);
}

// round 15
// speedup vs baseline: 2.0714x; 1.5522x over previous
#include <cuda_runtime.h>
#include <cuda_fp16.h>
#include <cstdint>

// Problem constants
#define B_SZ   16
#define CIN    128
#define COUT   128
#define HD     512
#define HW     128      // input H = W
#define OHW    126      // output H = W (VALID conv, K=3)
#define REM    1152     // CIN * 9
#define WSIZE  147456   // COUT * REM

// Single dynamic-smem symbol for the whole TU
extern __shared__ __align__(16) char dsm[];

// ---------------------------------------------------------------------------
// Device-global scratch (no allocation allowed anywhere)
// ---------------------------------------------------------------------------
// conv weights fp16, layout [b][co][k], k = tap*128 + ci (tap-major)
__device__ __align__(16) __half g_wh[B_SZ * WSIZE];
// x transposed to [b][ih][iw][ci] fp16 (+pad: conv may read past end)
__device__ __align__(16) __half g_xh[B_SZ * HW * HW * CIN + 1024];
__device__ float g_bias[B_SZ * COUT];

// ---------------------------------------------------------------------------
// helpers
// ---------------------------------------------------------------------------
__device__ __forceinline__ uint32_t smem_to_u32(const void* p) {
    uint32_t a;
    asm("{ .reg .u64 t; cvta.to.shared.u64 t, %1; cvt.u32.u64 %0, t; }"
        : "=r"(a) : "l"(p));
    return a;
}
__device__ __forceinline__ void cp16(void* dst, const void* src) {
    uint32_t d = smem_to_u32(dst);
    asm volatile("cp.async.cg.shared.global [%0], [%1], 16;"
                 :: "r"(d), "l"(src) : "memory");
}
#define CP_COMMIT()  asm volatile("cp.async.commit_group;" ::: "memory")
#define CP_WAIT(n)   asm volatile("cp.async.wait_group %0;" :: "n"(n) : "memory")

// mma.sync m16n8k16 row.col fp16 -> f32 accumulate
__device__ __forceinline__ void mma16816(float* c, const uint32_t* a,
                                         const uint32_t* b) {
    asm volatile(
        "mma.sync.aligned.m16n8k16.row.col.f32.f16.f16.f32 "
        "{%0,%1,%2,%3}, {%4,%5,%6,%7}, {%8,%9}, {%0,%1,%2,%3};"
        : "+f"(c[0]), "+f"(c[1]), "+f"(c[2]), "+f"(c[3])
        : "r"(a[0]), "r"(a[1]), "r"(a[2]), "r"(a[3]), "r"(b[0]), "r"(b[1]));
}

// f32x2 helpers (hyper GEMM keeps the proven FFMA2 path)
__device__ __forceinline__ void fma2(unsigned long long& d,
                                     unsigned long long a, unsigned long long b) {
    asm("fma.rn.f32x2 %0, %1, %2, %0;" : "+l"(d) : "l"(a), "l"(b));
}
__device__ __forceinline__ unsigned long long dup2(float v) {
    unsigned long long r; unsigned u = __float_as_uint(v);
    asm("mov.b64 %0, {%1, %1};" : "=l"(r) : "r"(u));
    return r;
}
__device__ __forceinline__ void unpack2(unsigned long long v, float& lo, float& hi) {
    asm("mov.b64 {%0, %1}, %2;" : "=f"(lo), "=f"(hi) : "l"(v));
}

// ---------------------------------------------------------------------------
// Kernel 1: hyper GEMM.  w[b,n] = h[b]·Wh[n] + bh[n]  (proven, ~106us)
// Epilogue writes fp16 into g_wh at [b][co][k], k = tap*128 + ci.
// ---------------------------------------------------------------------------
__global__ __launch_bounds__(256, 1)
void hyper_gemm_kernel(const float* __restrict__ Wh,
                       const float* __restrict__ h,
                       const float* __restrict__ bh) {
    float* sw = reinterpret_cast<float*>(dsm);               // [1024][33]
    float* hs = reinterpret_cast<float*>(dsm) + 1024 * 33;   // [32][16]

    const int t  = threadIdx.x;
    const int n0 = blockIdx.x * 1024;

    unsigned long long acc[32];
#pragma unroll
    for (int i = 0; i < 32; i++) acc[i] = 0ULL;

    for (int k0 = 0; k0 < HD; k0 += 32) {
        __syncthreads();
#pragma unroll
        for (int q = 0; q < 2; q++) {
            int idx = t + q * 256;
            hs[idx] = h[(idx & 15) * HD + k0 + (idx >> 4)];
        }
#pragma unroll
        for (int r = 0; r < 32; r++) {
            int linear = r * 256 + t;
            int n = linear >> 3, c = linear & 7;
            float4 v = reinterpret_cast<const float4*>(Wh)
                           [(size_t)(n0 + n) * (HD / 4) + (k0 >> 2) + c];
            float* dst = sw + n * 33 + c * 4;
            dst[0] = v.x; dst[1] = v.y; dst[2] = v.z; dst[3] = v.w;
        }
        __syncthreads();

#pragma unroll
        for (int kk = 0; kk < 32; kk++) {
            unsigned long long hv[8];
            const unsigned long long* hp =
                reinterpret_cast<const unsigned long long*>(hs + kk * 16);
#pragma unroll
            for (int bb = 0; bb < 8; bb++) hv[bb] = hp[bb];
            unsigned long long wv[4];
#pragma unroll
            for (int j = 0; j < 4; j++)
                wv[j] = dup2(sw[(t + 256 * j) * 33 + kk]);
#pragma unroll
            for (int bb = 0; bb < 8; bb++)
#pragma unroll
                for (int j = 0; j < 4; j++)
                    fma2(acc[bb * 4 + j], hv[bb], wv[j]);
        }
    }

#pragma unroll
    for (int j = 0; j < 4; j++) {
        int n   = n0 + t + 256 * j;
        float bv = bh[n];
        int co  = n / REM;
        int rem = n - co * REM;
        int ci  = rem / 9;
        int tap = rem - ci * 9;
        int k   = tap * 128 + ci;
#pragma unroll
        for (int bb = 0; bb < 8; bb++) {
            float lo, hi;
            unpack2(acc[bb * 4 + j], lo, hi);
            g_wh[((size_t)((2 * bb)     * COUT + co)) * REM + k] =
                __float2half_rn(lo + bv);
            g_wh[((size_t)((2 * bb + 1) * COUT + co)) * REM + k] =
                __float2half_rn(hi + bv);
        }
    }
}

// ---------------------------------------------------------------------------
// Kernel 2: x transpose NCHW -> [b][ih][iw][ci], fp16
// ---------------------------------------------------------------------------
__global__ __launch_bounds__(256)
void xpose_kernel(const float* __restrict__ x) {
    __shared__ float ts[32][33];
    const int ih = blockIdx.x, b = blockIdx.y;
    const int t = threadIdx.x, j = t & 31, g = t >> 5;

    for (int cit = 0; cit < 4; cit++)
        for (int iwt = 0; iwt < 4; iwt++) {
            __syncthreads();
#pragma unroll
            for (int ii = 0; ii < 4; ii++) {
                int ci = cit * 32 + g + ii * 8;
                ts[g + ii * 8][j] =
                    x[(((size_t)b * CIN + ci) * HW + ih) * HW + iwt * 32 + j];
            }
            __syncthreads();
#pragma unroll
            for (int ii = 0; ii < 4; ii++) {
                int iwl = g + ii * 8;
                size_t dst = (((size_t)b * HW + ih) * HW + iwt * 32 + iwl) * CIN
                             + cit * 32 + j;
                g_xh[dst] = __float2half_rn(ts[j][iwl]);
            }
        }
}

// ---------------------------------------------------------------------------
// Kernel 3: per-sample bias (unchanged)
// ---------------------------------------------------------------------------
__global__ void hyper_bias_kernel(const float* __restrict__ h,
                                  const float* __restrict__ Wb,
                                  const float* __restrict__ bb) {
    int out  = blockIdx.x * 8 + (threadIdx.x >> 5);
    int lane = threadIdx.x & 31;
    int b  = out >> 7;
    int co = out & 127;
    float s = 0.f;
    for (int k = lane; k < HD; k += 32)
        s += h[b * HD + k] * Wb[co * HD + k];
#pragma unroll
    for (int o = 16; o > 0; o >>= 1) s += __shfl_xor_sync(0xffffffffu, s, o);
    if (lane == 0) g_bias[out] = s + bb[co];
}

// ---------------------------------------------------------------------------
// Kernel 4: HMMA conv, single-pass fp16 (w*x), half the MMAs of R14.
// CTA = (oh, b): M=128 co x N=128 ow, K=1152 tap-major. 256 thr, 8 warps,
// warp tile 64x32. 18 chunks of KC=64, cp.async double buffer.
// Stage = 2 matrices (A|B) = 36.9KB; both buffers 73.7KB -> 2 CTAs/SM.
// ---------------------------------------------------------------------------
#define NCH   18
#define AROW  72                 // fp16 elems per smem row (64 data + 8 pad)
#define MATE  (128 * AROW)       // elems per matrix  (9216)
#define STGE  (2 * MATE)         // elems per stage   (A|B)
#define CONV_SMEM (2 * STGE * 2) // bytes = 73728

__global__ __launch_bounds__(256, 2)
void conv_mma_kernel(float* __restrict__ y) {
    __half* sm = reinterpret_cast<__half*>(dsm);
    const int t    = threadIdx.x;
    const int lane = t & 31, wid = t >> 5;
    const int g    = lane >> 2, tq = lane & 3;
    const int wrow = wid >> 2, wcol = wid & 3;   // 2x4 warp grid
    const int oh   = blockIdx.x;        // 0..125
    const int b    = blockIdx.y;        // 0..15

    const __half* whp = g_wh + (size_t)b * WSIZE;

    float acc[4][4][4];
#pragma unroll
    for (int mi = 0; mi < 4; mi++)
#pragma unroll
        for (int ni = 0; ni < 4; ni++)
#pragma unroll
            for (int q = 0; q < 4; q++) acc[mi][ni][q] = 0.f;

    auto load_stage = [&](int s, int kc) {
        const int tap = kc >> 1, ci0 = (kc & 1) * 64;
        const int kh = tap / 3, kw = tap - 3 * kh;
        __half* st = sm + s * STGE;
        const size_t xoff = (((size_t)(b * HW) + oh + kh) * HW + kw) * CIN + ci0;
        const __half* xh = g_xh + xoff;
#pragma unroll
        for (int i = 0; i < 4; i++) {
            int idx = t + i * 256;
            int row = idx >> 3, c = idx & 7;    // row: co or px; c: 16B column
            int so = row * AROW + c * 8;
            cp16(st + so,        whp + row * REM + kc * 64 + c * 8);
            cp16(st + MATE + so, xh + (size_t)row * CIN + c * 8);
        }
        CP_COMMIT();
    };

    load_stage(0, 0);

    for (int kc = 0; kc < NCH; kc++) {
        if (kc + 1 < NCH) { load_stage((kc + 1) & 1, kc + 1); CP_WAIT(1); }
        else              { CP_WAIT(0); }
        __syncthreads();

        const __half* st = sm + (kc & 1) * STGE;
        const __half* Ah = st;
        const __half* Bx = st + MATE;

#pragma unroll
        for (int ks = 0; ks < 4; ks++) {
            const int kw0 = ks * 16 + 2 * tq;
            uint32_t ahf[4][4], bf[4][2];
#pragma unroll
            for (int mi = 0; mi < 4; mi++) {
                int r0 = wrow * 64 + mi * 16 + g;
                const __half* p0 = Ah + r0 * AROW + kw0;
                ahf[mi][0] = *(const uint32_t*)p0;
                ahf[mi][1] = *(const uint32_t*)(p0 + 8 * AROW);
                ahf[mi][2] = *(const uint32_t*)(p0 + 8);
                ahf[mi][3] = *(const uint32_t*)(p0 + 8 * AROW + 8);
            }
#pragma unroll
            for (int ni = 0; ni < 4; ni++) {
                int n0 = wcol * 32 + ni * 8 + g;
                const __half* p0 = Bx + n0 * AROW + kw0;
                bf[ni][0] = *(const uint32_t*)p0;
                bf[ni][1] = *(const uint32_t*)(p0 + 8);
            }
#pragma unroll
            for (int mi = 0; mi < 4; mi++)
#pragma unroll
                for (int ni = 0; ni < 4; ni++)
                    mma16816(acc[mi][ni], ahf[mi], bf[ni]);
        }
        __syncthreads();
    }

    // Epilogue: + per-sample bias, guarded stores (ow < 126)
    const float* bp = g_bias + b * COUT;
#pragma unroll
    for (int mi = 0; mi < 4; mi++) {
        int co0 = wrow * 64 + mi * 16 + g;       // c0/c1 rows; c2/c3 at co0+8
        float bias0 = bp[co0], bias1 = bp[co0 + 8];
        float* y0 = y + (((size_t)(b * COUT) + co0) * OHW + oh) * OHW;
        float* y1 = y0 + (size_t)8 * OHW * OHW;
#pragma unroll
        for (int ni = 0; ni < 4; ni++) {
            int ow = wcol * 32 + ni * 8 + 2 * tq;
            if (ow < OHW) {
                y0[ow] = acc[mi][ni][0] + bias0;
                y1[ow] = acc[mi][ni][2] + bias1;
            }
            if (ow + 1 < OHW) {
                y0[ow + 1] = acc[mi][ni][1] + bias0;
                y1[ow + 1] = acc[mi][ni][3] + bias1;
            }
        }
    }
}

// ---------------------------------------------------------------------------
// Launch. Inputs: x, h, Wh, bh, Wb, bb. Output float32.
// ---------------------------------------------------------------------------
extern "C" void kernel_launch(void* const* d_in, const int* in_sizes, int n_in,
                              void* d_out, int out_size) {
    const float* x  = (const float*)d_in[0];
    const float* h  = (const float*)d_in[1];
    const float* Wh = (const float*)d_in[2];
    const float* bh = (const float*)d_in[3];
    const float* Wb = (const float*)d_in[4];
    const float* bb = (const float*)d_in[5];
    float* y = (float*)d_out;

    const int gemm_smem = (1024 * 33 + 32 * 16) * (int)sizeof(float);  // 137216
    cudaFuncSetAttribute(hyper_gemm_kernel,
                         cudaFuncAttributeMaxDynamicSharedMemorySize, gemm_smem);
    cudaFuncSetAttribute(conv_mma_kernel,
                         cudaFuncAttributeMaxDynamicSharedMemorySize, CONV_SMEM);

    hyper_gemm_kernel<<<WSIZE / 1024, 256, gemm_smem>>>(Wh, h, bh);
    xpose_kernel<<<dim3(HW, B_SZ), 256>>>(x);
    hyper_bias_kernel<<<(B_SZ * COUT) / 8, 256>>>(h, Wb, bb);
    conv_mma_kernel<<<dim3(OHW, B_SZ), 256, CONV_SMEM>>>(y);
}